// round 5
// baseline (speedup 1.0000x reference)
#include <cuda_runtime.h>
#include <cstdint>

// ---------------------------------------------------------------------------
// GraphCNNSequential: node/edge embed + 3x GCNConv + mean-pool + MLP head
// edge_index/batch are INT32 (confirmed: int64 reads in R3 produced fused
// garbage indices -> address-space trap; JAX x64 disabled).
// ---------------------------------------------------------------------------

#define MAXN 100000
#define MAXE 1600000
#define MAXG 512

// -------- scratch (static __device__ globals; no allocation allowed) --------
__device__ float g_h  [MAXN * 64];
__device__ float g_h2 [MAXN * 64];
__device__ float g_hw [MAXN * 64];
__device__ int   g_rcnt[MAXN];
__device__ int   g_ccnt[MAXN];
__device__ int   g_roff[MAXN + 1];
__device__ int   g_coff[MAXN + 1];
__device__ int   g_rcur[MAXN];
__device__ int   g_ccur[MAXN];
__device__ int   g_relist[MAXE];   // edge ids grouped by source (row)
__device__ int   g_csrc [MAXE];    // source node ids grouped by target (col)
__device__ float g_dinv [MAXN];
__device__ float g_psum [MAXG * 64];
__device__ float g_pcnt [MAXG];

// buffer selector (resolved in device code)
__device__ __forceinline__ float* buf(int sel) {
    switch (sel) {
        case 0:  return g_h;
        case 1:  return g_h2;
        default: return g_hw;
    }
}

// ---------------------------------------------------------------------------
// zero scratch counters (kernel, not memset — capture-safe)
// ---------------------------------------------------------------------------
__global__ void k_zero(int n, int g) {
    int i = blockIdx.x * blockDim.x + threadIdx.x;
    if (i < n)      { g_rcnt[i] = 0; g_ccnt[i] = 0; }
    if (i < g * 64) g_psum[i] = 0.0f;
    if (i < g)      g_pcnt[i] = 0.0f;
}

// ---------------------------------------------------------------------------
// CSR construction (edge_index: int32, [2,E] with row 0 = src, row 1 = dst)
// ---------------------------------------------------------------------------
__global__ void k_count(const int* __restrict__ ei, int E) {
    int e = blockIdx.x * blockDim.x + threadIdx.x;
    if (e >= E) return;
    int r = ei[e];
    int c = ei[E + e];
    if ((unsigned)r < (unsigned)MAXN) atomicAdd(&g_rcnt[r], 1);
    if ((unsigned)c < (unsigned)MAXN) atomicAdd(&g_ccnt[c], 1);
}

// single-block chunked exclusive scan: g_rcnt->g_roff (mode 0), g_ccnt->g_coff (mode 1)
__global__ void k_scan(int n, int mode) {
    const int* __restrict__ cnt = mode ? g_ccnt : g_rcnt;
    int* __restrict__ off       = mode ? g_coff : g_roff;
    __shared__ int part[1024];
    int tid = threadIdx.x;
    int chunk = (n + 1023) >> 10;
    int lo = tid * chunk;
    int hi = min(lo + chunk, n);
    int s = 0;
    for (int i = lo; i < hi; i++) s += cnt[i];
    part[tid] = s;
    __syncthreads();
    int mysum = s;
    for (int d = 1; d < 1024; d <<= 1) {
        int v = (tid >= d) ? part[tid - d] : 0;
        __syncthreads();
        part[tid] += v;
        __syncthreads();
    }
    int run = part[tid] - mysum;     // exclusive prefix for this chunk
    for (int i = lo; i < hi; i++) { off[i] = run; run += cnt[i]; }
    if (tid == 1023) off[n] = part[1023];
}

__global__ void k_prep(int n) {
    int i = blockIdx.x * blockDim.x + threadIdx.x;
    if (i >= n) return;
    g_rcur[i] = g_roff[i];
    g_ccur[i] = g_coff[i];
    g_dinv[i] = rsqrtf((float)(g_ccnt[i] + 1));   // deg = in-degree + self-loop
}

__global__ void k_fill(const int* __restrict__ ei, int E) {
    int e = blockIdx.x * blockDim.x + threadIdx.x;
    if (e >= E) return;
    int r = ei[e];
    int c = ei[E + e];
    if ((unsigned)r < (unsigned)MAXN) {
        int p = atomicAdd(&g_rcur[r], 1);
        g_relist[p] = e;
    }
    if ((unsigned)c < (unsigned)MAXN) {
        int q = atomicAdd(&g_ccur[c], 1);
        g_csrc[q] = r;
    }
}

// ---------------------------------------------------------------------------
// Node embed GEMM: g_h[n,64] = x[n,128] @ Wn[128,64] + bn. 4x4 register tile.
// ---------------------------------------------------------------------------
__global__ __launch_bounds__(128) void k_matmul_node(
    const float* __restrict__ A, const float* __restrict__ W,
    const float* __restrict__ bias, int n)
{
    const int ID = 128;
    __shared__ float Ws[ID * 64];
    __shared__ float Xs[32][ID];
    int tid = threadIdx.x;
    for (int i = tid; i < ID * 64; i += 128) Ws[i] = W[i];
    int n0 = blockIdx.x * 32;
    for (int i = tid; i < 32 * ID; i += 128) {
        int r = i >> 7, k = i & 127;
        int node = n0 + r;
        Xs[r][k] = (node < n) ? A[node * ID + k] : 0.0f;
    }
    __syncthreads();

    int tx = tid & 15;
    int ty = tid >> 4;
    float acc[4][4];
#pragma unroll
    for (int i = 0; i < 4; i++) {
        float b = bias[tx + 16 * i];
#pragma unroll
        for (int j = 0; j < 4; j++) acc[j][i] = b;
    }
#pragma unroll 8
    for (int k = 0; k < ID; k++) {
        float xv[4], wv[4];
#pragma unroll
        for (int j = 0; j < 4; j++) xv[j] = Xs[ty * 4 + j][k];
#pragma unroll
        for (int i = 0; i < 4; i++) wv[i] = Ws[k * 64 + tx + 16 * i];
#pragma unroll
        for (int j = 0; j < 4; j++)
#pragma unroll
            for (int i = 0; i < 4; i++) acc[j][i] += xv[j] * wv[i];
    }
#pragma unroll
    for (int j = 0; j < 4; j++) {
        int node = n0 + ty * 4 + j;
        if (node < n) {
#pragma unroll
            for (int i = 0; i < 4; i++) g_h[node * 64 + tx + 16 * i] = acc[j][i];
        }
    }
}

// ---------------------------------------------------------------------------
// Hidden GEMM: g_hw[n,64] = buf(src)[n,64] @ W[64,64] (no bias).
// ---------------------------------------------------------------------------
__global__ __launch_bounds__(128) void k_matmul_h(
    int src, const float* __restrict__ W, int n)
{
    const int ID = 64;
    const float* __restrict__ A = buf(src);
    __shared__ float Ws[ID * 64];
    __shared__ float Xs[32][ID + 1];
    int tid = threadIdx.x;
    for (int i = tid; i < ID * 64; i += 128) Ws[i] = W[i];
    int n0 = blockIdx.x * 32;
    for (int i = tid; i < 32 * ID; i += 128) {
        int r = i >> 6, k = i & 63;
        int node = n0 + r;
        Xs[r][k] = (node < n) ? A[node * ID + k] : 0.0f;
    }
    __syncthreads();

    int tx = tid & 15;
    int ty = tid >> 4;
    float acc[4][4];
#pragma unroll
    for (int i = 0; i < 4; i++)
#pragma unroll
        for (int j = 0; j < 4; j++) acc[j][i] = 0.0f;
#pragma unroll 8
    for (int k = 0; k < ID; k++) {
        float xv[4], wv[4];
#pragma unroll
        for (int j = 0; j < 4; j++) xv[j] = Xs[ty * 4 + j][k];
#pragma unroll
        for (int i = 0; i < 4; i++) wv[i] = Ws[k * 64 + tx + 16 * i];
#pragma unroll
        for (int j = 0; j < 4; j++)
#pragma unroll
            for (int i = 0; i < 4; i++) acc[j][i] += xv[j] * wv[i];
    }
#pragma unroll
    for (int j = 0; j < 4; j++) {
        int node = n0 + ty * 4 + j;
        if (node < n) {
#pragma unroll
            for (int i = 0; i < 4; i++) g_hw[node * 64 + tx + 16 * i] = acc[j][i];
        }
    }
}

// ---------------------------------------------------------------------------
// Edge embedding fused via linearity:
//   g_h[i] += (sum_{e: src=i} edge_attr[e]) @ W_edge + outdeg(i) * b_edge
// ---------------------------------------------------------------------------
__global__ __launch_bounds__(256) void k_edge_embed(
    const float* __restrict__ eattr, const float* __restrict__ We,
    const float* __restrict__ be, int n)
{
    __shared__ float Ws[32 * 64];
    int tid = threadIdx.x;
    for (int i = tid; i < 32 * 64; i += blockDim.x) Ws[i] = We[i];
    __syncthreads();
    int lane = tid & 31;
    int node = (blockIdx.x * blockDim.x + tid) >> 5;
    if (node >= n) return;
    int lo = g_roff[node], hi = g_roff[node + 1];
    float s = 0.0f;
    for (int idx = lo; idx < hi; idx++) {
        int e = g_relist[idx];
        s += eattr[e * 32 + lane];          // 128B coalesced gather
    }
    float a0 = 0.0f, a1 = 0.0f;
#pragma unroll
    for (int k = 0; k < 32; k++) {
        float sk = __shfl_sync(0xffffffffu, s, k);
        a0 += sk * Ws[k * 64 + lane];
        a1 += sk * Ws[k * 64 + 32 + lane];
    }
    float deg = (float)(hi - lo);
    g_h[node * 64 + lane]      += a0 + deg * be[lane];
    g_h[node * 64 + 32 + lane] += a1 + deg * be[32 + lane];
}

// ---------------------------------------------------------------------------
// GCN aggregation (gather form, float2-vectorized):
//   out[i] = relu?( bias + dinv[i]*( dinv[i]*hw[i] + sum_src dinv[src]*hw[src] ) )
// One warp per node; lane covers dims (2*lane, 2*lane+1) via float2.
// ---------------------------------------------------------------------------
__global__ __launch_bounds__(256) void k_aggregate(
    const float* __restrict__ bias, int dst, int n, int relu)
{
    float2* __restrict__ out = reinterpret_cast<float2*>(buf(dst));
    const float2* __restrict__ hw = reinterpret_cast<const float2*>(g_hw);
    int tid = threadIdx.x;
    int lane = tid & 31;
    int node = (blockIdx.x * blockDim.x + tid) >> 5;
    if (node >= n) return;
    float di = g_dinv[node];
    float2 self = hw[node * 32 + lane];
    float a0 = di * self.x;
    float a1 = di * self.y;
    int lo = g_coff[node], hi = g_coff[node + 1];
    for (int idx = lo; idx < hi; idx++) {
        int s = g_csrc[idx];
        float ds = g_dinv[s];
        float2 v = hw[s * 32 + lane];
        a0 += ds * v.x;
        a1 += ds * v.y;
    }
    float r0 = di * a0 + bias[2 * lane];
    float r1 = di * a1 + bias[2 * lane + 1];
    if (relu) { r0 = fmaxf(r0, 0.0f); r1 = fmaxf(r1, 0.0f); }
    out[node * 32 + lane] = make_float2(r0, r1);
}

// ---------------------------------------------------------------------------
// Mean pool from buf(src): sorted int32 batch -> warp handles 16 consecutive
// nodes, merging same-graph runs locally before flushing atomics.
// ---------------------------------------------------------------------------
__global__ __launch_bounds__(256) void k_pool(
    int src, const int* __restrict__ batch, int n)
{
    const float* __restrict__ h = buf(src);
    int lane = threadIdx.x & 31;
    int warp = (blockIdx.x * blockDim.x + threadIdx.x) >> 5;
    int base = warp * 16;
    if (base >= n) return;
    int end = min(base + 16, n);
    int cur = batch[base];
    float a0 = 0.0f, a1 = 0.0f;
    int run = 0;
    for (int i = base; i < end; i++) {
        int b = batch[i];
        if (b != cur) {
            atomicAdd(&g_psum[cur * 64 + lane], a0);
            atomicAdd(&g_psum[cur * 64 + 32 + lane], a1);
            if (lane == 0) atomicAdd(&g_pcnt[cur], (float)run);
            a0 = 0.0f; a1 = 0.0f; run = 0; cur = b;
        }
        a0 += h[i * 64 + lane];
        a1 += h[i * 64 + 32 + lane];
        run++;
    }
    atomicAdd(&g_psum[cur * 64 + lane], a0);
    atomicAdd(&g_psum[cur * 64 + 32 + lane], a1);
    if (lane == 0) atomicAdd(&g_pcnt[cur], (float)run);
}

// ---------------------------------------------------------------------------
// Classifier: out[g] = relu(mean_g @ Wc1 + bc1) @ Wc2 + bc2 ; warp per graph
// ---------------------------------------------------------------------------
__global__ __launch_bounds__(256) void k_classifier(
    const float* __restrict__ Wc1, const float* __restrict__ bc1,
    const float* __restrict__ Wc2, const float* __restrict__ bc2,
    float* __restrict__ out, int ng)
{
    int lane = threadIdx.x & 31;
    int g = (blockIdx.x * blockDim.x + threadIdx.x) >> 5;
    if (g >= ng) return;
    float inv = 1.0f / fmaxf(g_pcnt[g], 1.0f);
    float hj = bc1[lane];
#pragma unroll 8
    for (int k = 0; k < 64; k++)
        hj += g_psum[g * 64 + k] * inv * Wc1[k * 32 + lane];
    hj = fmaxf(hj, 0.0f);
    float v = hj * Wc2[lane];
#pragma unroll
    for (int o = 16; o > 0; o >>= 1) v += __shfl_down_sync(0xffffffffu, v, o);
    if (lane == 0) out[g] = v + bc2[0];
}

// ---------------------------------------------------------------------------
extern "C" void kernel_launch(void* const* d_in, const int* in_sizes, int n_in,
                              void* d_out, int out_size)
{
    const float* x     = (const float*)d_in[0];
    const int*   ei    = (const int*)d_in[1];     // int32 (confirmed via R3 trap)
    const float* eattr = (const float*)d_in[2];
    const int*   batch = (const int*)d_in[3];     // int32
    const float* Wn  = (const float*)d_in[4],  *bn  = (const float*)d_in[5];
    const float* We  = (const float*)d_in[6],  *be  = (const float*)d_in[7];
    const float* Wg1 = (const float*)d_in[8],  *bg1 = (const float*)d_in[9];
    const float* Wg2 = (const float*)d_in[10], *bg2 = (const float*)d_in[11];
    const float* Wg3 = (const float*)d_in[12], *bg3 = (const float*)d_in[13];
    const float* Wc1 = (const float*)d_in[14], *bc1 = (const float*)d_in[15];
    const float* Wc2 = (const float*)d_in[16], *bc2 = (const float*)d_in[17];
    float* out = (float*)d_out;

    int N = in_sizes[0] / 128;
    int E = in_sizes[1] / 2;
    int G = out_size;

    // zero counters/accumulators
    k_zero<<<(N + 255) / 256, 256>>>(N, G);

    // CSR build
    k_count<<<(E + 255) / 256, 256>>>(ei, E);
    k_scan<<<1, 1024>>>(N, 0);   // g_rcnt -> g_roff
    k_scan<<<1, 1024>>>(N, 1);   // g_ccnt -> g_coff
    k_prep<<<(N + 255) / 256, 256>>>(N);
    k_fill<<<(E + 255) / 256, 256>>>(ei, E);

    int mm_blocks  = (N + 31) / 32;
    int wpn_blocks = (N + 7) / 8;   // warp-per-node kernels, 256 thr = 8 warps

    // node embed + fused edge embed  (g_h = x@Wn + bn ; g_h += edge agg)
    k_matmul_node<<<mm_blocks, 128>>>(x, Wn, bn, N);
    k_edge_embed<<<wpn_blocks, 256>>>(eattr, We, be, N);

    // GCN layer 1: g_hw = g_h @ Wg1 ; g_h2 = relu(agg + bg1)
    k_matmul_h<<<mm_blocks, 128>>>(0, Wg1, N);
    k_aggregate<<<wpn_blocks, 256>>>(bg1, 1, N, 1);

    // GCN layer 2: g_hw = g_h2 @ Wg2 ; g_h = relu(agg + bg2)
    k_matmul_h<<<mm_blocks, 128>>>(1, Wg2, N);
    k_aggregate<<<wpn_blocks, 256>>>(bg2, 0, N, 1);

    // GCN layer 3: g_hw = g_h @ Wg3 ; g_h2 = agg + bg3
    k_matmul_h<<<mm_blocks, 128>>>(0, Wg3, N);
    k_aggregate<<<wpn_blocks, 256>>>(bg3, 1, N, 0);

    // pool + head
    k_pool<<<((N + 15) / 16 + 7) / 8, 256>>>(1, batch, N);
    k_classifier<<<(G + 7) / 8, 256>>>(Wc1, bc1, Wc2, bc2, out, G);
}

// round 8
// speedup vs baseline: 1.3661x; 1.3661x over previous
#include <cuda_runtime.h>
#include <cstdint>

// ---------------------------------------------------------------------------
// GraphCNNSequential: node/edge embed + 3x GCNConv + mean-pool + MLP head
// R8 == R7 == R6 resubmit. The R6/R7 failures were container/broker-level
// (no kernel diagnostics; contrast R3's real device fault which produced a
// proper harness error). Delta vs last PASSING kernel (R5, 710.7us):
// serial 1-block scan (2x106us) -> 3-phase multi-block scan (~10us).
// ---------------------------------------------------------------------------

#define MAXN 100000
#define MAXE 1600000
#define MAXG 512
#define SCAN_TILE 4096            // 512 threads * 8 elems
#define MAXSB 64                  // max scan blocks per array

// -------- scratch (static __device__ globals; no allocation allowed) --------
__device__ float g_h  [MAXN * 64];
__device__ float g_h2 [MAXN * 64];
__device__ float g_hw [MAXN * 64];
__device__ int   g_rcnt[MAXN];
__device__ int   g_ccnt[MAXN];
__device__ int   g_roff[MAXN + 1];
__device__ int   g_coff[MAXN + 1];
__device__ int   g_rcur[MAXN];
__device__ int   g_ccur[MAXN];
__device__ int   g_relist[MAXE];   // edge ids grouped by source (row)
__device__ int   g_csrc [MAXE];    // source node ids grouped by target (col)
__device__ float g_dinv [MAXN];
__device__ float g_psum [MAXG * 64];
__device__ float g_pcnt [MAXG];
__device__ int   g_bsum0[MAXSB];
__device__ int   g_bsum1[MAXSB];

// buffer selector (resolved in device code)
__device__ __forceinline__ float* buf(int sel) {
    switch (sel) {
        case 0:  return g_h;
        case 1:  return g_h2;
        default: return g_hw;
    }
}

// ---------------------------------------------------------------------------
// zero scratch counters (kernel, not memset — capture-safe)
// ---------------------------------------------------------------------------
__global__ void k_zero(int n, int g) {
    int i = blockIdx.x * blockDim.x + threadIdx.x;
    if (i < n)      { g_rcnt[i] = 0; g_ccnt[i] = 0; }
    if (i < g * 64) g_psum[i] = 0.0f;
    if (i < g)      g_pcnt[i] = 0.0f;
}

// ---------------------------------------------------------------------------
// CSR construction (edge_index: int32, [2,E] with row 0 = src, row 1 = dst)
// ---------------------------------------------------------------------------
__global__ void k_count(const int* __restrict__ ei, int E) {
    int e = blockIdx.x * blockDim.x + threadIdx.x;
    if (e >= E) return;
    int r = ei[e];
    int c = ei[E + e];
    if ((unsigned)r < (unsigned)MAXN) atomicAdd(&g_rcnt[r], 1);
    if ((unsigned)c < (unsigned)MAXN) atomicAdd(&g_ccnt[c], 1);
}

// ---------------------------------------------------------------------------
// Multi-block exclusive scan, 3 phases.
// ---------------------------------------------------------------------------
__global__ __launch_bounds__(512) void k_scan_part(int n, int mode) {
    const int* __restrict__ cnt = mode ? g_ccnt : g_rcnt;
    __shared__ int sh[512];
    int tid = threadIdx.x;
    int base = blockIdx.x * SCAN_TILE + tid * 8;
    int s = 0;
#pragma unroll
    for (int j = 0; j < 8; j++) {
        int i = base + j;
        if (i < n) s += cnt[i];
    }
    sh[tid] = s;
    __syncthreads();
    for (int d = 256; d > 0; d >>= 1) {
        if (tid < d) sh[tid] += sh[tid + d];
        __syncthreads();
    }
    if (tid == 0) (mode ? g_bsum1 : g_bsum0)[blockIdx.x] = sh[0];
}

__global__ void k_scan_mid(int nb) {
    int tid = threadIdx.x;
    if (tid == 0) {
        int run = 0;
        for (int b = 0; b < nb; b++) { int v = g_bsum0[b]; g_bsum0[b] = run; run += v; }
    }
    if (tid == 1) {
        int run = 0;
        for (int b = 0; b < nb; b++) { int v = g_bsum1[b]; g_bsum1[b] = run; run += v; }
    }
}

__global__ __launch_bounds__(512) void k_scan_final(int n, int mode) {
    const int* __restrict__ cnt = mode ? g_ccnt : g_rcnt;
    int* __restrict__ off       = mode ? g_coff : g_roff;
    __shared__ int sh[512];
    int tid = threadIdx.x;
    int base = blockIdx.x * SCAN_TILE + tid * 8;
    int v[8];
    int s = 0;
#pragma unroll
    for (int j = 0; j < 8; j++) {
        int i = base + j;
        v[j] = (i < n) ? cnt[i] : 0;
        s += v[j];
    }
    sh[tid] = s;
    __syncthreads();
    // inclusive Hillis-Steele over 512 thread sums
    for (int d = 1; d < 512; d <<= 1) {
        int t = (tid >= d) ? sh[tid - d] : 0;
        __syncthreads();
        sh[tid] += t;
        __syncthreads();
    }
    int run = sh[tid] - s + (mode ? g_bsum1 : g_bsum0)[blockIdx.x];
#pragma unroll
    for (int j = 0; j < 8; j++) {
        int i = base + j;
        if (i < n) { off[i] = run; run += v[j]; }
        if (i == n - 1) off[n] = run;
    }
}

__global__ void k_prep(int n) {
    int i = blockIdx.x * blockDim.x + threadIdx.x;
    if (i >= n) return;
    g_rcur[i] = g_roff[i];
    g_ccur[i] = g_coff[i];
    g_dinv[i] = rsqrtf((float)(g_ccnt[i] + 1));   // deg = in-degree + self-loop
}

__global__ void k_fill(const int* __restrict__ ei, int E) {
    int e = blockIdx.x * blockDim.x + threadIdx.x;
    if (e >= E) return;
    int r = ei[e];
    int c = ei[E + e];
    if ((unsigned)r < (unsigned)MAXN) {
        int p = atomicAdd(&g_rcur[r], 1);
        g_relist[p] = e;
    }
    if ((unsigned)c < (unsigned)MAXN) {
        int q = atomicAdd(&g_ccur[c], 1);
        g_csrc[q] = r;
    }
}

// ---------------------------------------------------------------------------
// Node embed GEMM: g_h[n,64] = x[n,128] @ Wn[128,64] + bn. 4x4 register tile.
// ---------------------------------------------------------------------------
__global__ __launch_bounds__(128) void k_matmul_node(
    const float* __restrict__ A, const float* __restrict__ W,
    const float* __restrict__ bias, int n)
{
    const int ID = 128;
    __shared__ float Ws[ID * 64];
    __shared__ float Xs[32][ID];
    int tid = threadIdx.x;
    for (int i = tid; i < ID * 64; i += 128) Ws[i] = W[i];
    int n0 = blockIdx.x * 32;
    for (int i = tid; i < 32 * ID; i += 128) {
        int r = i >> 7, k = i & 127;
        int node = n0 + r;
        Xs[r][k] = (node < n) ? A[node * ID + k] : 0.0f;
    }
    __syncthreads();

    int tx = tid & 15;
    int ty = tid >> 4;
    float acc[4][4];
#pragma unroll
    for (int i = 0; i < 4; i++) {
        float b = bias[tx + 16 * i];
#pragma unroll
        for (int j = 0; j < 4; j++) acc[j][i] = b;
    }
#pragma unroll 8
    for (int k = 0; k < ID; k++) {
        float xv[4], wv[4];
#pragma unroll
        for (int j = 0; j < 4; j++) xv[j] = Xs[ty * 4 + j][k];
#pragma unroll
        for (int i = 0; i < 4; i++) wv[i] = Ws[k * 64 + tx + 16 * i];
#pragma unroll
        for (int j = 0; j < 4; j++)
#pragma unroll
            for (int i = 0; i < 4; i++) acc[j][i] += xv[j] * wv[i];
    }
#pragma unroll
    for (int j = 0; j < 4; j++) {
        int node = n0 + ty * 4 + j;
        if (node < n) {
#pragma unroll
            for (int i = 0; i < 4; i++) g_h[node * 64 + tx + 16 * i] = acc[j][i];
        }
    }
}

// ---------------------------------------------------------------------------
// Hidden GEMM: g_hw[n,64] = buf(src)[n,64] @ W[64,64] (no bias).
// ---------------------------------------------------------------------------
__global__ __launch_bounds__(128) void k_matmul_h(
    int src, const float* __restrict__ W, int n)
{
    const int ID = 64;
    const float* __restrict__ A = buf(src);
    __shared__ float Ws[ID * 64];
    __shared__ float Xs[32][ID + 1];
    int tid = threadIdx.x;
    for (int i = tid; i < ID * 64; i += 128) Ws[i] = W[i];
    int n0 = blockIdx.x * 32;
    for (int i = tid; i < 32 * ID; i += 128) {
        int r = i >> 6, k = i & 63;
        int node = n0 + r;
        Xs[r][k] = (node < n) ? A[node * ID + k] : 0.0f;
    }
    __syncthreads();

    int tx = tid & 15;
    int ty = tid >> 4;
    float acc[4][4];
#pragma unroll
    for (int i = 0; i < 4; i++)
#pragma unroll
        for (int j = 0; j < 4; j++) acc[j][i] = 0.0f;
#pragma unroll 8
    for (int k = 0; k < ID; k++) {
        float xv[4], wv[4];
#pragma unroll
        for (int j = 0; j < 4; j++) xv[j] = Xs[ty * 4 + j][k];
#pragma unroll
        for (int i = 0; i < 4; i++) wv[i] = Ws[k * 64 + tx + 16 * i];
#pragma unroll
        for (int j = 0; j < 4; j++)
#pragma unroll
            for (int i = 0; i < 4; i++) acc[j][i] += xv[j] * wv[i];
    }
#pragma unroll
    for (int j = 0; j < 4; j++) {
        int node = n0 + ty * 4 + j;
        if (node < n) {
#pragma unroll
            for (int i = 0; i < 4; i++) g_hw[node * 64 + tx + 16 * i] = acc[j][i];
        }
    }
}

// ---------------------------------------------------------------------------
// Edge embedding fused via linearity:
//   g_h[i] += (sum_{e: src=i} edge_attr[e]) @ W_edge + outdeg(i) * b_edge
// ---------------------------------------------------------------------------
__global__ __launch_bounds__(256) void k_edge_embed(
    const float* __restrict__ eattr, const float* __restrict__ We,
    const float* __restrict__ be, int n)
{
    __shared__ float Ws[32 * 64];
    int tid = threadIdx.x;
    for (int i = tid; i < 32 * 64; i += blockDim.x) Ws[i] = We[i];
    __syncthreads();
    int lane = tid & 31;
    int node = (blockIdx.x * blockDim.x + tid) >> 5;
    if (node >= n) return;
    int lo = g_roff[node], hi = g_roff[node + 1];
    float s = 0.0f;
    for (int idx = lo; idx < hi; idx++) {
        int e = g_relist[idx];
        s += eattr[e * 32 + lane];          // 128B coalesced gather
    }
    float a0 = 0.0f, a1 = 0.0f;
#pragma unroll
    for (int k = 0; k < 32; k++) {
        float sk = __shfl_sync(0xffffffffu, s, k);
        a0 += sk * Ws[k * 64 + lane];
        a1 += sk * Ws[k * 64 + 32 + lane];
    }
    float deg = (float)(hi - lo);
    g_h[node * 64 + lane]      += a0 + deg * be[lane];
    g_h[node * 64 + 32 + lane] += a1 + deg * be[32 + lane];
}

// ---------------------------------------------------------------------------
// GCN aggregation (gather form, float2-vectorized):
//   out[i] = relu?( bias + dinv[i]*( dinv[i]*hw[i] + sum_src dinv[src]*hw[src] ) )
// One warp per node; lane covers dims (2*lane, 2*lane+1) via float2.
// ---------------------------------------------------------------------------
__global__ __launch_bounds__(256) void k_aggregate(
    const float* __restrict__ bias, int dst, int n, int relu)
{
    float2* __restrict__ out = reinterpret_cast<float2*>(buf(dst));
    const float2* __restrict__ hw = reinterpret_cast<const float2*>(g_hw);
    int tid = threadIdx.x;
    int lane = tid & 31;
    int node = (blockIdx.x * blockDim.x + tid) >> 5;
    if (node >= n) return;
    float di = g_dinv[node];
    float2 self = hw[node * 32 + lane];
    float a0 = di * self.x;
    float a1 = di * self.y;
    int lo = g_coff[node], hi = g_coff[node + 1];
    for (int idx = lo; idx < hi; idx++) {
        int s = g_csrc[idx];
        float ds = g_dinv[s];
        float2 v = hw[s * 32 + lane];
        a0 += ds * v.x;
        a1 += ds * v.y;
    }
    float r0 = di * a0 + bias[2 * lane];
    float r1 = di * a1 + bias[2 * lane + 1];
    if (relu) { r0 = fmaxf(r0, 0.0f); r1 = fmaxf(r1, 0.0f); }
    out[node * 32 + lane] = make_float2(r0, r1);
}

// ---------------------------------------------------------------------------
// Mean pool from buf(src): sorted int32 batch -> warp handles 16 consecutive
// nodes, merging same-graph runs locally before flushing atomics.
// ---------------------------------------------------------------------------
__global__ __launch_bounds__(256) void k_pool(
    int src, const int* __restrict__ batch, int n)
{
    const float* __restrict__ h = buf(src);
    int lane = threadIdx.x & 31;
    int warp = (blockIdx.x * blockDim.x + threadIdx.x) >> 5;
    int base = warp * 16;
    if (base >= n) return;
    int end = min(base + 16, n);
    int cur = batch[base];
    float a0 = 0.0f, a1 = 0.0f;
    int run = 0;
    for (int i = base; i < end; i++) {
        int b = batch[i];
        if (b != cur) {
            atomicAdd(&g_psum[cur * 64 + lane], a0);
            atomicAdd(&g_psum[cur * 64 + 32 + lane], a1);
            if (lane == 0) atomicAdd(&g_pcnt[cur], (float)run);
            a0 = 0.0f; a1 = 0.0f; run = 0; cur = b;
        }
        a0 += h[i * 64 + lane];
        a1 += h[i * 64 + 32 + lane];
        run++;
    }
    atomicAdd(&g_psum[cur * 64 + lane], a0);
    atomicAdd(&g_psum[cur * 64 + 32 + lane], a1);
    if (lane == 0) atomicAdd(&g_pcnt[cur], (float)run);
}

// ---------------------------------------------------------------------------
// Classifier: out[g] = relu(mean_g @ Wc1 + bc1) @ Wc2 + bc2 ; warp per graph
// ---------------------------------------------------------------------------
__global__ __launch_bounds__(256) void k_classifier(
    const float* __restrict__ Wc1, const float* __restrict__ bc1,
    const float* __restrict__ Wc2, const float* __restrict__ bc2,
    float* __restrict__ out, int ng)
{
    int lane = threadIdx.x & 31;
    int g = (blockIdx.x * blockDim.x + threadIdx.x) >> 5;
    if (g >= ng) return;
    float inv = 1.0f / fmaxf(g_pcnt[g], 1.0f);
    float hj = bc1[lane];
#pragma unroll 8
    for (int k = 0; k < 64; k++)
        hj += g_psum[g * 64 + k] * inv * Wc1[k * 32 + lane];
    hj = fmaxf(hj, 0.0f);
    float v = hj * Wc2[lane];
#pragma unroll
    for (int o = 16; o > 0; o >>= 1) v += __shfl_down_sync(0xffffffffu, v, o);
    if (lane == 0) out[g] = v + bc2[0];
}

// ---------------------------------------------------------------------------
extern "C" void kernel_launch(void* const* d_in, const int* in_sizes, int n_in,
                              void* d_out, int out_size)
{
    const float* x     = (const float*)d_in[0];
    const int*   ei    = (const int*)d_in[1];     // int32
    const float* eattr = (const float*)d_in[2];
    const int*   batch = (const int*)d_in[3];     // int32
    const float* Wn  = (const float*)d_in[4],  *bn  = (const float*)d_in[5];
    const float* We  = (const float*)d_in[6],  *be  = (const float*)d_in[7];
    const float* Wg1 = (const float*)d_in[8],  *bg1 = (const float*)d_in[9];
    const float* Wg2 = (const float*)d_in[10], *bg2 = (const float*)d_in[11];
    const float* Wg3 = (const float*)d_in[12], *bg3 = (const float*)d_in[13];
    const float* Wc1 = (const float*)d_in[14], *bc1 = (const float*)d_in[15];
    const float* Wc2 = (const float*)d_in[16], *bc2 = (const float*)d_in[17];
    float* out = (float*)d_out;

    int N = in_sizes[0] / 128;
    int E = in_sizes[1] / 2;
    int G = out_size;
    int nsb = (N + SCAN_TILE - 1) / SCAN_TILE;    // scan blocks per array

    // zero counters/accumulators
    k_zero<<<(N + 255) / 256, 256>>>(N, G);

    // CSR build
    k_count<<<(E + 255) / 256, 256>>>(ei, E);
    k_scan_part<<<nsb, 512>>>(N, 0);
    k_scan_part<<<nsb, 512>>>(N, 1);
    k_scan_mid<<<1, 32>>>(nsb);
    k_scan_final<<<nsb, 512>>>(N, 0);
    k_scan_final<<<nsb, 512>>>(N, 1);
    k_prep<<<(N + 255) / 256, 256>>>(N);
    k_fill<<<(E + 255) / 256, 256>>>(ei, E);

    int mm_blocks  = (N + 31) / 32;
    int wpn_blocks = (N + 7) / 8;   // warp-per-node kernels, 256 thr = 8 warps

    // node embed + fused edge embed  (g_h = x@Wn + bn ; g_h += edge agg)
    k_matmul_node<<<mm_blocks, 128>>>(x, Wn, bn, N);
    k_edge_embed<<<wpn_blocks, 256>>>(eattr, We, be, N);

    // GCN layer 1: g_hw = g_h @ Wg1 ; g_h2 = relu(agg + bg1)
    k_matmul_h<<<mm_blocks, 128>>>(0, Wg1, N);
    k_aggregate<<<wpn_blocks, 256>>>(bg1, 1, N, 1);

    // GCN layer 2: g_hw = g_h2 @ Wg2 ; g_h = relu(agg + bg2)
    k_matmul_h<<<mm_blocks, 128>>>(1, Wg2, N);
    k_aggregate<<<wpn_blocks, 256>>>(bg2, 0, N, 1);

    // GCN layer 3: g_hw = g_h @ Wg3 ; g_h2 = agg + bg3
    k_matmul_h<<<mm_blocks, 128>>>(0, Wg3, N);
    k_aggregate<<<wpn_blocks, 256>>>(bg3, 1, N, 0);

    // pool + head
    k_pool<<<((N + 15) / 16 + 7) / 8, 256>>>(1, batch, N);
    k_classifier<<<(G + 7) / 8, 256>>>(Wc1, bc1, Wc2, bc2, out, G);
}